// round 1
// baseline (speedup 1.0000x reference)
#include <cuda_runtime.h>
#include <cuda_bf16.h>
#include <cstdint>

// Leaky RNN: x_t = 0.9*x_{t-1} + 0.1*(u@Win + tanh(x_{t-1})@Wrec + brec) + q_t
//            z_t = tanh(x_t)@Wout + bout
// T=1024, B=64, NIN=32, N=256, NOUT=16.
//
// Design: 128 CTAs = 64 batches x 2 cluster ranks (n-half split).
//   256 threads/CTA: thread = (jh in {0,1}, nl in [0,128)).
//   Wrec column slice held REGISTER-STATIONARY: thread owns Wrec[jh*128+k][rank*128+nl], k<128.
//   r-vector (256 floats) double-buffered in smem; own half written locally +
//   DSMEM-stored to the peer CTA each step; barrier.cluster per step.
//   Output projection z_t computed post-barrier by warp 0 (hides barrier wait).

#define T_STEPS 1024
#define B_SZ    64
#define N_IN    32
#define N_HID   256
#define N_OUT   16

__device__ __forceinline__ float ftanh(float x) {
    // tanh(x) = 1 - 2/(exp(2x)+1); robust at +/-inf, ~1e-6 rel err (MUFU-based)
    float e = __expf(2.0f * x);
    return 1.0f - __fdividef(2.0f, e + 1.0f);
}

__device__ __forceinline__ void st_shared_remote(float* p, float v, unsigned peer) {
    unsigned laddr = (unsigned)__cvta_generic_to_shared(p);
    unsigned raddr;
    asm volatile("mapa.shared::cluster.u32 %0, %1, %2;" : "=r"(raddr) : "r"(laddr), "r"(peer));
    asm volatile("st.shared::cluster.f32 [%0], %1;" :: "r"(raddr), "f"(v) : "memory");
}

#define CLUSTER_ARRIVE() asm volatile("barrier.cluster.arrive.aligned;" ::: "memory")
#define CLUSTER_WAIT()   asm volatile("barrier.cluster.wait.aligned;"   ::: "memory")

__global__ void __launch_bounds__(256, 1) __cluster_dims__(2, 1, 1)
rnn_kernel(const float* __restrict__ inputs,   // [T,B,NIN]
           const float* __restrict__ noise,    // [T,B,N]
           const float* __restrict__ x0,       // [B,N]
           const float* __restrict__ Win,      // [NIN,N]
           const float* __restrict__ Wrec,     // [N,N]
           const float* __restrict__ brec,     // [N]
           const float* __restrict__ Wout,     // [N,NOUT]
           const float* __restrict__ bout,     // [NOUT]
           float* __restrict__ outputs,        // [T,B,NOUT]
           float* __restrict__ states)         // [T,B,N]
{
    __shared__ __align__(16) float sWinT[128][36];   // WinT[nl][i], padded (9 odd -> cf LDS.128)
    __shared__ __align__(16) float sWoutT[16][260];  // WoutT[o][n], padded (65 odd)
    __shared__ __align__(16) float sRbuf[2][256];    // double-buffered full r vector
    __shared__ __align__(16) float sUbuf[2][32];     // double-buffered u_t
    __shared__ float sPcomb[128];                    // jh=1 partial sums
    __shared__ float sBout[16];

    const int tid  = threadIdx.x;
    const int b    = blockIdx.x >> 1;
    const unsigned rank = blockIdx.x & 1u;
    const int jh   = tid >> 7;           // j-half: 0 -> j in [0,128), 1 -> [128,256)
    const int nl   = tid & 127;          // local column
    const int gn   = (int)rank * 128 + nl; // global column owned (jh==0 owns state)

    // ---- register-stationary Wrec slice: w[k] = Wrec[jh*128+k][gn] ----
    float w[128];
    #pragma unroll
    for (int k = 0; k < 128; ++k)
        w[k] = Wrec[(jh * 128 + k) * N_HID + gn];

    // ---- smem init ----
    for (int idx = tid; idx < N_IN * 128; idx += 256) {
        int i = idx >> 7, n2 = idx & 127;
        sWinT[n2][i] = Win[i * N_HID + (int)rank * 128 + n2];
    }
    for (int idx = tid; idx < N_HID * N_OUT; idx += 256) {
        int n2 = idx >> 4, o = idx & 15;
        sWoutT[o][n2] = Wout[idx];
    }
    if (tid < 16) sBout[tid] = bout[tid];
    if (tid < 32) sUbuf[0][tid] = inputs[b * N_IN + tid];   // u_0

    float x = 0.0f, qreg = 0.0f, ureg = 0.0f, brec_r = 0.0f;
    if (jh == 0) {
        x = x0[b * N_HID + gn];
        float r0 = ftanh(x);
        sRbuf[0][gn] = r0;
        st_shared_remote(&sRbuf[0][gn], r0, rank ^ 1u);
        qreg = noise[b * N_HID + gn];                        // q_0
    } else {
        brec_r = brec[gn];
        if (nl < 32) ureg = inputs[1 * (B_SZ * N_IN) + b * N_IN + nl]; // u_1
    }

    CLUSTER_ARRIVE(); CLUSTER_WAIT();

    #pragma unroll 1
    for (int t = 0; t < T_STEPS; ++t) {
        const int par = t & 1;
        const int nb  = par ^ 1;

        // ---- recurrent partial over own j-half (weights in regs, r broadcast LDS) ----
        const float4* rp = reinterpret_cast<const float4*>(&sRbuf[par][jh << 7]);
        float a0 = 0.f, a1 = 0.f, a2 = 0.f, a3 = 0.f;
        #pragma unroll
        for (int g = 0; g < 32; ++g) {
            float4 r4 = rp[g];
            a0 = fmaf(w[4*g+0], r4.x, a0);
            a1 = fmaf(w[4*g+1], r4.y, a1);
            a2 = fmaf(w[4*g+2], r4.z, a2);
            a3 = fmaf(w[4*g+3], r4.w, a3);
        }
        float sum = (a0 + a1) + (a2 + a3);

        float qnext = 0.0f;
        if (jh) {
            // stage u_{t+1} (loaded last iter into ureg), prefetch u_{t+2}
            if (nl < 32) {
                sUbuf[nb][nl] = ureg;
                int tn = (t + 2 < T_STEPS) ? (t + 2) : (T_STEPS - 1);
                ureg = inputs[tn * (B_SZ * N_IN) + b * N_IN + nl];
            }
            // input projection u_t @ Win (vectorized from smem)
            float c0 = 0.f, c1 = 0.f, c2 = 0.f, c3 = 0.f;
            const float4* up = reinterpret_cast<const float4*>(&sUbuf[par][0]);
            const float4* wp = reinterpret_cast<const float4*>(&sWinT[nl][0]);
            #pragma unroll
            for (int gi = 0; gi < 8; ++gi) {
                float4 u4 = up[gi]; float4 w4 = wp[gi];
                c0 = fmaf(u4.x, w4.x, c0); c1 = fmaf(u4.y, w4.y, c1);
                c2 = fmaf(u4.z, w4.z, c2); c3 = fmaf(u4.w, w4.w, c3);
            }
            sPcomb[nl] = sum + ((c0 + c1) + (c2 + c3)) + brec_r;
        } else {
            int tn = (t + 1 < T_STEPS) ? (t + 1) : (T_STEPS - 1);
            qnext = noise[tn * (B_SZ * N_HID) + b * N_HID + gn];  // prefetch q_{t+1}
        }
        __syncthreads();

        if (!jh) {
            float tot = sum + sPcomb[nl];
            x = 0.9f * x + 0.1f * tot + qreg;
            qreg = qnext;
            float rt = ftanh(x);
            states[t * (B_SZ * N_HID) + b * N_HID + gn] = x;
            sRbuf[nb][gn] = rt;
            st_shared_remote(&sRbuf[nb][gn], rt, rank ^ 1u);
        }

        CLUSTER_ARRIVE(); CLUSTER_WAIT();

        // ---- z_t = r_t @ Wout + bout, warp 0 only (runs in barrier shadow) ----
        if (tid < 32) {
            int oo  = ((int)rank << 3) + (tid >> 2);  // rank0: o 0..7, rank1: o 8..15
            int seg = tid & 3;                        // n-quarter
            const float4* rz = reinterpret_cast<const float4*>(&sRbuf[nb][seg << 6]);
            const float4* wz = reinterpret_cast<const float4*>(&sWoutT[oo][seg << 6]);
            float z0 = 0.f, z1 = 0.f, z2 = 0.f, z3 = 0.f;
            #pragma unroll
            for (int g = 0; g < 16; ++g) {
                float4 r4 = rz[g]; float4 w4 = wz[g];
                z0 = fmaf(r4.x, w4.x, z0); z1 = fmaf(r4.y, w4.y, z1);
                z2 = fmaf(r4.z, w4.z, z2); z3 = fmaf(r4.w, w4.w, z3);
            }
            float zz = (z0 + z1) + (z2 + z3);
            zz += __shfl_xor_sync(0xffffffffu, zz, 1);
            zz += __shfl_xor_sync(0xffffffffu, zz, 2);
            if (seg == 0)
                outputs[t * (B_SZ * N_OUT) + b * N_OUT + oo] = zz + sBout[oo];
        }
    }
}

extern "C" void kernel_launch(void* const* d_in, const int* in_sizes, int n_in,
                              void* d_out, int out_size) {
    const float* inputs = (const float*)d_in[0];
    const float* noise  = (const float*)d_in[1];
    const float* x0     = (const float*)d_in[2];
    const float* Win    = (const float*)d_in[3];
    const float* Wrec   = (const float*)d_in[4];
    const float* brec   = (const float*)d_in[5];
    const float* Wout   = (const float*)d_in[6];
    const float* bout   = (const float*)d_in[7];

    float* outputs = (float*)d_out;                              // [T,B,NOUT]
    float* states  = (float*)d_out + (size_t)T_STEPS * B_SZ * N_OUT; // [T,B,N]

    rnn_kernel<<<dim3(B_SZ * 2), dim3(256)>>>(
        inputs, noise, x0, Win, Wrec, brec, Wout, bout, outputs, states);
}